// round 9
// baseline (speedup 1.0000x reference)
#include <cuda_runtime.h>
#include <cuda_bf16.h>
#include <math.h>
#include <stdint.h>

constexpr int N = 50000;
constexpr int E = 800000;

// ---------------------------------------------------------------------------
// Device scratch (BSS zero at load; kernels restore zeros for graph replay)
// ---------------------------------------------------------------------------
__device__ __align__(16) uint32_t g_xb [N * 64];   // x as bf16x2 (128 ch)
__device__ __align__(16) float g_nbr[N * 128];
__device__ __align__(16) float g_h  [N * 128];
__device__ __align__(16) uint32_t g_z1b[N * 32];   // z1 as bf16x2 (64 ch)
__device__ __align__(16) uint32_t g_z2b[N * 32];   // z2 as bf16x2
__device__ __align__(16) float g_as1[N * 8];
__device__ __align__(16) float g_ad1[N * 8];
__device__ __align__(16) float g_h2 [N * 64];
__device__ float g_as2[N];          // zeroed by gat1 each run
__device__ float g_ad2[N];
__device__ float g_out_acc;         // zeroed by gat2 last block
__device__ unsigned g_done;         // zeroed by gat2 last block
__device__ float g_bwr;             // dot(b2, Wr), written by scan
__device__ int g_deg[N];            // zeroed by scan each run
__device__ int g_off[N + 1];
__device__ unsigned long long g_pack[E];
__device__ int g_csr[E];

// ---------------------------------------------------------------------------
// Helpers
// ---------------------------------------------------------------------------
__device__ __forceinline__ float lrelu(float x) { return x > 0.f ? x : 0.2f * x; }
__device__ __forceinline__ float elu1(float x)  { return x > 0.f ? x : __expf(x) - 1.f; }

__device__ __forceinline__ uint32_t f2tf32(float x) {
    uint32_t r;
    asm("cvt.rna.tf32.f32 %0, %1;" : "=r"(r) : "f"(x));
    return r;
}

__device__ __forceinline__ uint32_t pack_bf16(float a, float b) {
    __nv_bfloat162 v = __float22bfloat162_rn(make_float2(a, b));
    return *reinterpret_cast<uint32_t*>(&v);
}
__device__ __forceinline__ float2 unpack_bf16(uint32_t u) {
    return __bfloat1622float2(*reinterpret_cast<__nv_bfloat162*>(&u));
}

__device__ __forceinline__ void mma_tf32(float c[4], const uint4& a, const uint2& b) {
    asm volatile(
        "mma.sync.aligned.m16n8k8.row.col.f32.tf32.tf32.f32 "
        "{%0,%1,%2,%3}, {%4,%5,%6,%7}, {%8,%9}, {%0,%1,%2,%3};"
        : "+f"(c[0]), "+f"(c[1]), "+f"(c[2]), "+f"(c[3])
        : "r"(a.x), "r"(a.y), "r"(a.z), "r"(a.w), "r"(b.x), "r"(b.y));
}

// ---------------------------------------------------------------------------
// hist: x->bf16 convert (grid-stride) + local dtype detect + degree histogram
// writing packed (src | dst<<16 | rank<<32) per edge
// ---------------------------------------------------------------------------
__global__ void hist_kernel(const void* __restrict__ ei, const float* __restrict__ x) {
    __shared__ int s_any;
    const int tid = threadIdx.x;
    const int gstride = gridDim.x * blockDim.x;
    for (int t = blockIdx.x * blockDim.x + tid; t < N * 64; t += gstride) {
        float2 v = ((const float2*)x)[t];
        g_xb[t] = pack_bf16(v.x, v.y);
    }
    if (tid == 0) s_any = 0;
    __syncthreads();
    const int* ei32 = (const int*)ei;
    int any = 0;
    for (int t = tid; t < 1024; t += blockDim.x) any |= ei32[2 * t + 1];
    if (any) atomicOr(&s_any, 1);
    __syncthreads();
    const bool is64 = (s_any == 0);

    int e = blockIdx.x * blockDim.x + tid;
    if (e >= E) return;
    int s, d;
    if (is64) {
        s = (int)((const long long*)ei)[e];
        d = (int)((const long long*)ei)[(long long)E + e];
    } else {
        s = ei32[e];
        d = ei32[E + e];
    }
    unsigned rank = atomicAdd(&g_deg[d], 1);
    g_pack[e] = (unsigned long long)(unsigned)s
              | ((unsigned long long)(unsigned)d << 16)
              | ((unsigned long long)rank << 32);
}

// ---------------------------------------------------------------------------
// scan: exclusive prefix of g_deg -> g_off[0..N], zero g_deg, compute b2.Wr
// ---------------------------------------------------------------------------
__global__ void scan_kernel(const float* __restrict__ b2, const float* __restrict__ Wr) {
    __shared__ int wsum[32];
    __shared__ int s_carry;
    __shared__ float s_bwr[2];
    int tid = threadIdx.x, lane = tid & 31, wid = tid >> 5;
    if (wid < 2) {
        float v = b2[tid] * Wr[tid];
#pragma unroll
        for (int o = 16; o; o >>= 1) v += __shfl_xor_sync(0xffffffff, v, o);
        if (lane == 0) s_bwr[wid] = v;
    }
    if (tid == 0) s_carry = 0;
    __syncthreads();
    if (tid == 0) g_bwr = s_bwr[0] + s_bwr[1];
    for (int base = 0; base < N; base += 1024) {
        int i = base + tid;
        int v = (i < N) ? g_deg[i] : 0;
        int s = v;
#pragma unroll
        for (int o = 1; o < 32; o <<= 1) {
            int u = __shfl_up_sync(0xffffffff, s, o);
            if (lane >= o) s += u;
        }
        if (lane == 31) wsum[wid] = s;
        __syncthreads();
        if (wid == 0) {
            int w = wsum[lane];
#pragma unroll
            for (int o = 1; o < 32; o <<= 1) {
                int u = __shfl_up_sync(0xffffffff, w, o);
                if (lane >= o) w += u;
            }
            wsum[lane] = w;
        }
        __syncthreads();
        int prev = (wid > 0) ? wsum[wid - 1] : 0;
        int carry = s_carry;
        if (i < N) { g_off[i] = carry + prev + s - v; g_deg[i] = 0; }
        __syncthreads();
        if (tid == 1023) s_carry = carry + wsum[31];
        __syncthreads();
    }
    if (tid == 0) g_off[N] = s_carry;
}

// ---------------------------------------------------------------------------
// fill: one 8B packed read per edge, atomic-free scatter
// ---------------------------------------------------------------------------
__global__ void fill_kernel() {
    int e = blockIdx.x * blockDim.x + threadIdx.x;
    if (e >= E) return;
    unsigned long long p = g_pack[e];
    int s    = (int)(p & 0xffffu);
    int d    = (int)((p >> 16) & 0xffffu);
    int rank = (int)(p >> 32);
    g_csr[g_off[d] + rank] = s;
}

// ---------------------------------------------------------------------------
// GraphConv gather: quarter-warp per edge, bf16 x, fp32 accum
// ---------------------------------------------------------------------------
__global__ void gather_nbr_kernel() {
    int gid = blockIdx.x * blockDim.x + threadIdx.x;
    int node = gid >> 5, lane = gid & 31;
    if (node >= N) return;
    int beg = g_off[node], deg = g_off[node + 1] - beg;
    const int q = lane >> 3, l8 = lane & 7;

    float acc[16];
#pragma unroll
    for (int j = 0; j < 16; j++) acc[j] = 0.f;

    int k = q;
    for (; k + 4 < deg; k += 8) {
        int s0 = g_csr[beg + k], s1 = g_csr[beg + k + 4];
        uint4 a0 = *(const uint4*)&g_xb[(size_t)s0 * 64 + l8 * 8];
        uint4 b0 = *(const uint4*)&g_xb[(size_t)s0 * 64 + l8 * 8 + 4];
        uint4 a1 = *(const uint4*)&g_xb[(size_t)s1 * 64 + l8 * 8];
        uint4 b1 = *(const uint4*)&g_xb[(size_t)s1 * 64 + l8 * 8 + 4];
        const uint32_t u0[8] = {a0.x,a0.y,a0.z,a0.w,b0.x,b0.y,b0.z,b0.w};
        const uint32_t u1[8] = {a1.x,a1.y,a1.z,a1.w,b1.x,b1.y,b1.z,b1.w};
#pragma unroll
        for (int j = 0; j < 8; j++) {
            float2 p0 = unpack_bf16(u0[j]), p1 = unpack_bf16(u1[j]);
            acc[j*2]   += p0.x + p1.x;
            acc[j*2+1] += p0.y + p1.y;
        }
    }
    if (k < deg) {
        int s = g_csr[beg + k];
        uint4 a = *(const uint4*)&g_xb[(size_t)s * 64 + l8 * 8];
        uint4 b = *(const uint4*)&g_xb[(size_t)s * 64 + l8 * 8 + 4];
        const uint32_t u[8] = {a.x,a.y,a.z,a.w,b.x,b.y,b.z,b.w};
#pragma unroll
        for (int j = 0; j < 8; j++) {
            float2 p = unpack_bf16(u[j]);
            acc[j*2] += p.x; acc[j*2+1] += p.y;
        }
    }
#pragma unroll
    for (int j = 0; j < 16; j++) {
        acc[j] += __shfl_xor_sync(0xffffffff, acc[j], 8);
        acc[j] += __shfl_xor_sync(0xffffffff, acc[j], 16);
    }
    if (q == 0) {
        float* dst = g_nbr + (size_t)node * 128 + l8 * 16;
#pragma unroll
        for (int j = 0; j < 4; j++)
            *(float4*)(dst + j * 4) = make_float4(acc[j*4], acc[j*4+1], acc[j*4+2], acc[j*4+3]);
    }
}

// ---------------------------------------------------------------------------
// tf32 GEMM. MODE 0: fp32 out + bias + optional ELU.
//           MODE 1: bf16 out + per-head alpha (as1/ad1).
//           MODE 2: bf16 out + single-head alpha partials via atomicAdd.
// ---------------------------------------------------------------------------
template<int BN, int MODE>
__global__ __launch_bounds__(256) void tf32_linear(
    const float* __restrict__ A1, const float* __restrict__ Wa, int K1,
    const float* __restrict__ A2, const float* __restrict__ Wb, int K2,
    const float* __restrict__ bias, void* __restrict__ Cout,
    const float* __restrict__ aS, const float* __restrict__ aD,
    int M, int NCOL, int act)
{
    constexpr int NT = BN / 16;
    __shared__ __align__(16) uint32_t As[4][8][128];
    __shared__ __align__(16) uint32_t Bs[4][BN / 8][64];
    const int tid  = threadIdx.x;
    const int lane = tid & 31, warp = tid >> 5;
    const int wm = warp & 3, wn = warp >> 2;
    const int row0 = blockIdx.x * 128, c0 = blockIdx.y * BN;

    float acc[2][NT][4];
#pragma unroll
    for (int mt = 0; mt < 2; mt++)
#pragma unroll
        for (int nt = 0; nt < NT; nt++)
#pragma unroll
            for (int j = 0; j < 4; j++) acc[mt][nt][j] = 0.f;

    const int nk1 = K1 >> 5;
    const int nk2 = A2 ? (K2 >> 5) : 0;
    for (int t = 0; t < nk1 + nk2; t++) {
        const float* A; const float* W; int K, kb;
        if (t < nk1) { A = A1; W = Wa; K = K1; kb = t << 5; }
        else         { A = A2; W = Wb; K = K2; kb = (t - nk1) << 5; }
        __syncthreads();
#pragma unroll
        for (int i = 0; i < 4; i++) {
            int idx = tid + i * 256;
            int m = idx >> 3, k4 = (idx & 7) << 2;
            float4 v = make_float4(0.f, 0.f, 0.f, 0.f);
            if (row0 + m < M) v = *(const float4*)(A + (size_t)(row0 + m) * K + kb + k4);
            float vv[4] = {v.x, v.y, v.z, v.w};
            int m16 = m >> 4, mm = m & 15, r = mm & 7, rr = mm >> 3;
#pragma unroll
            for (int j = 0; j < 4; j++) {
                int k = k4 + j;
                int reg = ((k & 7) >> 2) * 2 + rr;
                As[k >> 3][m16][(r * 4 + (k & 3)) * 4 + reg] = f2tf32(vv[j]);
            }
        }
#pragma unroll
        for (int i = 0; i < BN / 32; i++) {
            int idx = tid + i * 256;
            int n = idx >> 3, k4 = (idx & 7) << 2;
            float4 v = *(const float4*)(W + (size_t)(c0 + n) * K + kb + k4);
            float vv[4] = {v.x, v.y, v.z, v.w};
            int n8 = n >> 3, nn = n & 7;
#pragma unroll
            for (int j = 0; j < 4; j++) {
                int k = k4 + j;
                Bs[k >> 3][n8][(nn * 4 + (k & 3)) * 2 + ((k & 7) >> 2)] = f2tf32(vv[j]);
            }
        }
        __syncthreads();
#pragma unroll
        for (int k8 = 0; k8 < 4; k8++) {
            uint4 a[2];
            uint2 b[NT];
            a[0] = *(const uint4*)&As[k8][wm * 2 + 0][lane * 4];
            a[1] = *(const uint4*)&As[k8][wm * 2 + 1][lane * 4];
#pragma unroll
            for (int nt = 0; nt < NT; nt++)
                b[nt] = *(const uint2*)&Bs[k8][wn * NT + nt][lane * 2];
#pragma unroll
            for (int mt = 0; mt < 2; mt++)
#pragma unroll
                for (int nt = 0; nt < NT; nt++)
                    mma_tf32(acc[mt][nt], a[mt], b[nt]);
        }
    }

    const int r = lane >> 2, cc = (lane & 3) * 2;
#pragma unroll
    for (int mt = 0; mt < 2; mt++) {
        int row  = row0 + (wm * 2 + mt) * 16 + r;
        int row2 = row + 8;
        float psl = 0.f, pdl = 0.f, psh = 0.f, pdh = 0.f;
#pragma unroll
        for (int nt = 0; nt < NT; nt++) {
            int col = c0 + (wn * NT + nt) * 8 + cc;
            float v0 = acc[mt][nt][0], v1 = acc[mt][nt][1];
            float v2 = acc[mt][nt][2], v3 = acc[mt][nt][3];
            if (MODE == 0) {
                float bx = 0.f, by = 0.f;
                if (bias) { bx = bias[col]; by = bias[col + 1]; }
                float* C = (float*)Cout;
                if (row < M) {
                    float a0 = v0 + bx, a1 = v1 + by;
                    if (act == 1) { a0 = elu1(a0); a1 = elu1(a1); }
                    *(float2*)(C + (size_t)row * NCOL + col) = make_float2(a0, a1);
                }
                if (row2 < M) {
                    float a2 = v2 + bx, a3 = v3 + by;
                    if (act == 1) { a2 = elu1(a2); a3 = elu1(a3); }
                    *(float2*)(C + (size_t)row2 * NCOL + col) = make_float2(a2, a3);
                }
            } else {
                uint32_t* Zb = (uint32_t*)Cout;
                if (row  < M) Zb[(size_t)row  * 32 + (col >> 1)] = pack_bf16(v0, v1);
                if (row2 < M) Zb[(size_t)row2 * 32 + (col >> 1)] = pack_bf16(v2, v3);
                float s0 = aS[col], s1 = aS[col + 1];
                float d0 = aD[col], d1 = aD[col + 1];
                if (MODE == 1) {
                    int h = wn * NT + nt;
                    float ps_lo = v0 * s0 + v1 * s1;
                    float pd_lo = v0 * d0 + v1 * d1;
                    float ps_hi = v2 * s0 + v3 * s1;
                    float pd_hi = v2 * d0 + v3 * d1;
                    ps_lo += __shfl_xor_sync(0xffffffff, ps_lo, 1);
                    ps_lo += __shfl_xor_sync(0xffffffff, ps_lo, 2);
                    pd_lo += __shfl_xor_sync(0xffffffff, pd_lo, 1);
                    pd_lo += __shfl_xor_sync(0xffffffff, pd_lo, 2);
                    ps_hi += __shfl_xor_sync(0xffffffff, ps_hi, 1);
                    ps_hi += __shfl_xor_sync(0xffffffff, ps_hi, 2);
                    pd_hi += __shfl_xor_sync(0xffffffff, pd_hi, 1);
                    pd_hi += __shfl_xor_sync(0xffffffff, pd_hi, 2);
                    if ((lane & 3) == 0) {
                        if (row  < M) { g_as1[(size_t)row  * 8 + h] = ps_lo; g_ad1[(size_t)row  * 8 + h] = pd_lo; }
                        if (row2 < M) { g_as1[(size_t)row2 * 8 + h] = ps_hi; g_ad1[(size_t)row2 * 8 + h] = pd_hi; }
                    }
                } else {
                    psl += v0 * s0 + v1 * s1;
                    pdl += v0 * d0 + v1 * d1;
                    psh += v2 * s0 + v3 * s1;
                    pdh += v2 * d0 + v3 * d1;
                }
            }
        }
        if (MODE == 2) {
            psl += __shfl_xor_sync(0xffffffff, psl, 1);
            psl += __shfl_xor_sync(0xffffffff, psl, 2);
            pdl += __shfl_xor_sync(0xffffffff, pdl, 1);
            pdl += __shfl_xor_sync(0xffffffff, pdl, 2);
            psh += __shfl_xor_sync(0xffffffff, psh, 1);
            psh += __shfl_xor_sync(0xffffffff, psh, 2);
            pdh += __shfl_xor_sync(0xffffffff, pdh, 1);
            pdh += __shfl_xor_sync(0xffffffff, pdh, 2);
            if ((lane & 3) == 0) {
                if (row  < M) { atomicAdd(&g_as2[row],  psl); atomicAdd(&g_ad2[row],  pdl); }
                if (row2 < M) { atomicAdd(&g_as2[row2], psh); atomicAdd(&g_ad2[row2], pdh); }
            }
        }
    }
}

// ---------------------------------------------------------------------------
// GAT1 fused: quarter-warp per edge, 4 edges in flight; zeroes as2/ad2
// ---------------------------------------------------------------------------
__global__ void gat1_fused(const float* __restrict__ b1) {
    int gid = blockIdx.x * blockDim.x + threadIdx.x;
    int node = gid >> 5, lane = gid & 31;
    if (node >= N) return;
    int beg = g_off[node], deg = g_off[node + 1] - beg;
    const int q = lane >> 3, l8 = lane & 7;
    const float adh = g_ad1[(size_t)node * 8 + l8];
    if (lane == 0) { g_as2[node] = 0.f; g_ad2[node] = 0.f; }

    float acc[8];
#pragma unroll
    for (int j = 0; j < 8; j++) acc[j] = 0.f;
    float den = 0.f;

    if (q == 0) {  // self-loop
        float w = __expf(lrelu(g_as1[(size_t)node * 8 + l8] + adh));
        uint4 u = *(const uint4*)&g_z1b[(size_t)node * 32 + l8 * 4];
        const uint32_t uu[4] = {u.x, u.y, u.z, u.w};
#pragma unroll
        for (int j = 0; j < 4; j++) {
            float2 p = unpack_bf16(uu[j]);
            acc[j*2] = w * p.x; acc[j*2+1] = w * p.y;
        }
        den = w;
    }
    int k = q;
    for (; k + 12 < deg; k += 16) {
        int s0 = g_csr[beg + k],     s1 = g_csr[beg + k + 4];
        int s2 = g_csr[beg + k + 8], s3 = g_csr[beg + k + 12];
        float w0 = __expf(lrelu(g_as1[(size_t)s0 * 8 + l8] + adh));
        float w1 = __expf(lrelu(g_as1[(size_t)s1 * 8 + l8] + adh));
        float w2 = __expf(lrelu(g_as1[(size_t)s2 * 8 + l8] + adh));
        float w3 = __expf(lrelu(g_as1[(size_t)s3 * 8 + l8] + adh));
        uint4 u0 = *(const uint4*)&g_z1b[(size_t)s0 * 32 + l8 * 4];
        uint4 u1 = *(const uint4*)&g_z1b[(size_t)s1 * 32 + l8 * 4];
        uint4 u2 = *(const uint4*)&g_z1b[(size_t)s2 * 32 + l8 * 4];
        uint4 u3 = *(const uint4*)&g_z1b[(size_t)s3 * 32 + l8 * 4];
        const uint32_t a0[4] = {u0.x,u0.y,u0.z,u0.w};
        const uint32_t a1[4] = {u1.x,u1.y,u1.z,u1.w};
        const uint32_t a2[4] = {u2.x,u2.y,u2.z,u2.w};
        const uint32_t a3[4] = {u3.x,u3.y,u3.z,u3.w};
#pragma unroll
        for (int j = 0; j < 4; j++) {
            float2 p0 = unpack_bf16(a0[j]), p1 = unpack_bf16(a1[j]);
            float2 p2 = unpack_bf16(a2[j]), p3 = unpack_bf16(a3[j]);
            acc[j*2]   += w0*p0.x + w1*p1.x + w2*p2.x + w3*p3.x;
            acc[j*2+1] += w0*p0.y + w1*p1.y + w2*p2.y + w3*p3.y;
        }
        den += w0 + w1 + w2 + w3;
    }
    for (; k < deg; k += 4) {
        int s = g_csr[beg + k];
        float w = __expf(lrelu(g_as1[(size_t)s * 8 + l8] + adh));
        uint4 u = *(const uint4*)&g_z1b[(size_t)s * 32 + l8 * 4];
        const uint32_t uu[4] = {u.x, u.y, u.z, u.w};
#pragma unroll
        for (int j = 0; j < 4; j++) {
            float2 p = unpack_bf16(uu[j]);
            acc[j*2] += w * p.x; acc[j*2+1] += w * p.y;
        }
        den += w;
    }
#pragma unroll
    for (int j = 0; j < 8; j++) {
        acc[j] += __shfl_xor_sync(0xffffffff, acc[j], 8);
        acc[j] += __shfl_xor_sync(0xffffffff, acc[j], 16);
    }
    den += __shfl_xor_sync(0xffffffff, den, 8);
    den += __shfl_xor_sync(0xffffffff, den, 16);
    if (q == 0) {
        float rh = 1.f / (den + 1e-16f);
        float* dst = g_h2 + (size_t)node * 64 + l8 * 8;
        const float* bb = b1 + l8 * 8;
#pragma unroll
        for (int j = 0; j < 2; j++) {
            float4 bv = *(const float4*)(bb + j * 4);
            *(float4*)(dst + j * 4) = make_float4(
                elu1(acc[j*4]   * rh + bv.x), elu1(acc[j*4+1] * rh + bv.y),
                elu1(acc[j*4+2] * rh + bv.z), elu1(acc[j*4+3] * rh + bv.w));
        }
    }
}

// ---------------------------------------------------------------------------
// GAT2 fused + regression head; last block finalizes output
// ---------------------------------------------------------------------------
__global__ void gat2_fused(const float* __restrict__ Wr, const float* __restrict__ br,
                           float* __restrict__ out) {
    __shared__ float bp[8];
    int gid = blockIdx.x * blockDim.x + threadIdx.x;
    int node = gid >> 5, lane = gid & 31, wid = threadIdx.x >> 5;
    int beg = g_off[node], deg = g_off[node + 1] - beg;
    const int q = lane >> 3, l8 = lane & 7;
    const float adn = g_ad2[node];

    float acc[8];
#pragma unroll
    for (int j = 0; j < 8; j++) acc[j] = 0.f;
    float den = 0.f;

    if (q == 0) {
        float w = __expf(lrelu(g_as2[node] + adn));
        uint4 u = *(const uint4*)&g_z2b[(size_t)node * 32 + l8 * 4];
        const uint32_t uu[4] = {u.x, u.y, u.z, u.w};
#pragma unroll
        for (int j = 0; j < 4; j++) {
            float2 p = unpack_bf16(uu[j]);
            acc[j*2] = w * p.x; acc[j*2+1] = w * p.y;
        }
        den = w;
    }
    int k = q;
    for (; k + 12 < deg; k += 16) {
        int s0 = g_csr[beg + k],     s1 = g_csr[beg + k + 4];
        int s2 = g_csr[beg + k + 8], s3 = g_csr[beg + k + 12];
        float w0 = __expf(lrelu(g_as2[s0] + adn));
        float w1 = __expf(lrelu(g_as2[s1] + adn));
        float w2 = __expf(lrelu(g_as2[s2] + adn));
        float w3 = __expf(lrelu(g_as2[s3] + adn));
        uint4 u0 = *(const uint4*)&g_z2b[(size_t)s0 * 32 + l8 * 4];
        uint4 u1 = *(const uint4*)&g_z2b[(size_t)s1 * 32 + l8 * 4];
        uint4 u2 = *(const uint4*)&g_z2b[(size_t)s2 * 32 + l8 * 4];
        uint4 u3 = *(const uint4*)&g_z2b[(size_t)s3 * 32 + l8 * 4];
        const uint32_t a0[4] = {u0.x,u0.y,u0.z,u0.w};
        const uint32_t a1[4] = {u1.x,u1.y,u1.z,u1.w};
        const uint32_t a2[4] = {u2.x,u2.y,u2.z,u2.w};
        const uint32_t a3[4] = {u3.x,u3.y,u3.z,u3.w};
#pragma unroll
        for (int j = 0; j < 4; j++) {
            float2 p0 = unpack_bf16(a0[j]), p1 = unpack_bf16(a1[j]);
            float2 p2 = unpack_bf16(a2[j]), p3 = unpack_bf16(a3[j]);
            acc[j*2]   += w0*p0.x + w1*p1.x + w2*p2.x + w3*p3.x;
            acc[j*2+1] += w0*p0.y + w1*p1.y + w2*p2.y + w3*p3.y;
        }
        den += w0 + w1 + w2 + w3;
    }
    for (; k < deg; k += 4) {
        int s = g_csr[beg + k];
        float w = __expf(lrelu(g_as2[s] + adn));
        uint4 u = *(const uint4*)&g_z2b[(size_t)s * 32 + l8 * 4];
        const uint32_t uu[4] = {u.x, u.y, u.z, u.w};
#pragma unroll
        for (int j = 0; j < 4; j++) {
            float2 p = unpack_bf16(uu[j]);
            acc[j*2] += w * p.x; acc[j*2+1] += w * p.y;
        }
        den += w;
    }
#pragma unroll
    for (int j = 0; j < 8; j++) {
        acc[j] += __shfl_xor_sync(0xffffffff, acc[j], 8);
        acc[j] += __shfl_xor_sync(0xffffffff, acc[j], 16);
    }
    den += __shfl_xor_sync(0xffffffff, den, 8);
    den += __shfl_xor_sync(0xffffffff, den, 16);

    float pd = 0.f;
    const float* wp = Wr + l8 * 8;
#pragma unroll
    for (int j = 0; j < 8; j++) pd += acc[j] * wp[j];
    pd += __shfl_xor_sync(0xffffffff, pd, 1);
    pd += __shfl_xor_sync(0xffffffff, pd, 2);
    pd += __shfl_xor_sync(0xffffffff, pd, 4);
    if (lane == 0) bp[wid] = pd / (den + 1e-16f);
    __syncthreads();
    if (threadIdx.x == 0) {
        float s = 0.f;
#pragma unroll
        for (int j = 0; j < 8; j++) s += bp[j];
        atomicAdd(&g_out_acc, s);
        __threadfence();
        unsigned old = atomicAdd(&g_done, 1u);
        if (old == gridDim.x - 1) {
            float total = atomicExch(&g_out_acc, 0.f);
            out[0] = total * (1.0f / (float)N) + g_bwr + br[0];
            g_done = 0;
        }
    }
}

// ---------------------------------------------------------------------------
// Launch
// ---------------------------------------------------------------------------
extern "C" void kernel_launch(void* const* d_in, const int* in_sizes, int n_in,
                              void* d_out, int out_size) {
    const float* x      = (const float*)d_in[0];
    const void*  ei     = d_in[1];
    const float* W_rel  = (const float*)d_in[2];
    const float* b_rel  = (const float*)d_in[3];
    const float* W_root = (const float*)d_in[4];
    const float* W1     = (const float*)d_in[5];
    const float* a1s    = (const float*)d_in[6];
    const float* a1d    = (const float*)d_in[7];
    const float* b1     = (const float*)d_in[8];
    const float* W2     = (const float*)d_in[9];
    const float* a2s    = (const float*)d_in[10];
    const float* a2d    = (const float*)d_in[11];
    const float* b2     = (const float*)d_in[12];
    const float* Wr     = (const float*)d_in[13];
    const float* br     = (const float*)d_in[14];
    float* out          = (float*)d_out;

    float *p_nbr, *p_h, *p_h2;
    void *p_z1b, *p_z2b;
    cudaGetSymbolAddress((void**)&p_nbr, g_nbr);
    cudaGetSymbolAddress((void**)&p_h,   g_h);
    cudaGetSymbolAddress(&p_z1b, g_z1b);
    cudaGetSymbolAddress((void**)&p_h2,  g_h2);
    cudaGetSymbolAddress(&p_z2b, g_z2b);

    hist_kernel<<<(E + 255) / 256, 256>>>(ei, x);
    scan_kernel<<<1, 1024>>>(b2, Wr);
    fill_kernel<<<(E + 255) / 256, 256>>>();

    gather_nbr_kernel<<<(N * 32 + 255) / 256, 256>>>();
    {
        dim3 g((N + 127) / 128, 1);
        tf32_linear<128, 0><<<g, 256>>>(p_nbr, W_rel, 128, x, W_root, 128,
                                        b_rel, p_h, nullptr, nullptr, N, 128, 1);
    }
    {
        dim3 g((N + 127) / 128, 1);
        tf32_linear<64, 1><<<g, 256>>>(p_h, W1, 128, nullptr, nullptr, 0,
                                       nullptr, p_z1b, a1s, a1d, N, 64, 0);
    }
    gat1_fused<<<(N * 32 + 255) / 256, 256>>>(b1);

    {
        dim3 g((N + 127) / 128, 1);
        tf32_linear<64, 2><<<g, 256>>>(p_h2, W2, 64, nullptr, nullptr, 0,
                                       nullptr, p_z2b, a2s, a2d, N, 64, 0);
    }
    gat2_fused<<<N * 32 / 256, 256>>>(Wr, br, out);
}

// round 10
// speedup vs baseline: 1.0359x; 1.0359x over previous
#include <cuda_runtime.h>
#include <cuda_bf16.h>
#include <math.h>
#include <stdint.h>

constexpr int N = 50000;
constexpr int E = 800000;

// ---------------------------------------------------------------------------
// Device scratch
// ---------------------------------------------------------------------------
__device__ __align__(16) uint32_t g_xb [N * 64];   // x as bf16x2 (128 ch)
__device__ __align__(16) float g_nbr[N * 128];
__device__ __align__(16) float g_h  [N * 128];
__device__ __align__(16) uint32_t g_z1b[N * 32];   // z1 as bf16x2 (64 ch)
__device__ __align__(16) uint32_t g_z2b[N * 32];   // z2 as bf16x2
__device__ __align__(16) float g_as1[N * 8];
__device__ __align__(16) float g_ad1[N * 8];
__device__ __align__(16) float g_h2 [N * 64];
__device__ float g_as2[N];
__device__ float g_ad2[N];
__device__ float g_out_acc;
__device__ int g_deg[N];
__device__ int g_off[N];
__device__ unsigned long long g_pack[E];
__device__ int g_csr[E];
__device__ int g_is64;

// ---------------------------------------------------------------------------
// Helpers
// ---------------------------------------------------------------------------
__device__ __forceinline__ float lrelu(float x) { return x > 0.f ? x : 0.2f * x; }
__device__ __forceinline__ float elu1(float x)  { return x > 0.f ? x : __expf(x) - 1.f; }

__device__ __forceinline__ uint32_t f2tf32(float x) {
    uint32_t r;
    asm("cvt.rna.tf32.f32 %0, %1;" : "=r"(r) : "f"(x));
    return r;
}

__device__ __forceinline__ uint32_t pack_bf16(float a, float b) {
    __nv_bfloat162 v = __float22bfloat162_rn(make_float2(a, b));
    return *reinterpret_cast<uint32_t*>(&v);
}
__device__ __forceinline__ float2 unpack_bf16(uint32_t u) {
    return __bfloat1622float2(*reinterpret_cast<__nv_bfloat162*>(&u));
}

__device__ __forceinline__ void mma_tf32(float c[4], const uint4& a, const uint2& b) {
    asm volatile(
        "mma.sync.aligned.m16n8k8.row.col.f32.tf32.tf32.f32 "
        "{%0,%1,%2,%3}, {%4,%5,%6,%7}, {%8,%9}, {%0,%1,%2,%3};"
        : "+f"(c[0]), "+f"(c[1]), "+f"(c[2]), "+f"(c[3])
        : "r"(a.x), "r"(a.y), "r"(a.z), "r"(a.w), "r"(b.x), "r"(b.y));
}

__device__ __forceinline__ int edge_id(const void* ei, long long idx) {
    return g_is64 ? (int)((const long long*)ei)[idx] : ((const int*)ei)[idx];
}
__device__ __forceinline__ int edge_src(const void* ei, int e) { return edge_id(ei, e); }
__device__ __forceinline__ int edge_dst(const void* ei, int e) { return edge_id(ei, (long long)E + e); }

// ---------------------------------------------------------------------------
// init: zero counters, convert x -> bf16, dtype detect (block 0)
// ---------------------------------------------------------------------------
__global__ void init_kernel(const int* ei, const float* __restrict__ x) {
    int i = blockIdx.x * blockDim.x + threadIdx.x;
    int stride = gridDim.x * blockDim.x;
    for (int t = i; t < N; t += stride) { g_deg[t] = 0; g_as2[t] = 0.f; g_ad2[t] = 0.f; }
    for (int t = i; t < N * 64; t += stride) {
        float2 v = ((const float2*)x)[t];
        g_xb[t] = pack_bf16(v.x, v.y);
    }
    if (i == 0) g_out_acc = 0.f;
    if (blockIdx.x == 0) {
        __shared__ int any;
        if (threadIdx.x == 0) any = 0;
        __syncthreads();
        for (int t = threadIdx.x; t < 1024; t += blockDim.x)
            if (ei[2 * t + 1] != 0) atomicOr(&any, 1);
        __syncthreads();
        if (threadIdx.x == 0) g_is64 = any ? 0 : 1;
    }
}

// ---------------------------------------------------------------------------
// CSR build: hist captures rank + packs (src|dst|rank); fill atomic-free 8B
// ---------------------------------------------------------------------------
__global__ void hist_kernel(const void* __restrict__ ei) {
    int e = blockIdx.x * blockDim.x + threadIdx.x;
    if (e >= E) return;
    int s = edge_src(ei, e), d = edge_dst(ei, e);
    unsigned rank = atomicAdd(&g_deg[d], 1);
    g_pack[e] = (unsigned long long)(unsigned)s
              | ((unsigned long long)(unsigned)d << 16)
              | ((unsigned long long)rank << 32);
}

__global__ void scan_kernel() {
    __shared__ int wsum[32];
    __shared__ int s_carry;
    int tid = threadIdx.x, lane = tid & 31, wid = tid >> 5;
    if (tid == 0) s_carry = 0;
    __syncthreads();
    for (int base = 0; base < N; base += 1024) {
        int i = base + tid;
        int v = (i < N) ? g_deg[i] : 0;
        int s = v;
#pragma unroll
        for (int o = 1; o < 32; o <<= 1) {
            int u = __shfl_up_sync(0xffffffff, s, o);
            if (lane >= o) s += u;
        }
        if (lane == 31) wsum[wid] = s;
        __syncthreads();
        if (wid == 0) {
            int w = wsum[lane];
#pragma unroll
            for (int o = 1; o < 32; o <<= 1) {
                int u = __shfl_up_sync(0xffffffff, w, o);
                if (lane >= o) w += u;
            }
            wsum[lane] = w;
        }
        __syncthreads();
        int prev = (wid > 0) ? wsum[wid - 1] : 0;
        int carry = s_carry;
        if (i < N) g_off[i] = carry + prev + s - v;
        __syncthreads();
        if (tid == 1023) s_carry = carry + wsum[31];
        __syncthreads();
    }
}

__global__ void fill_kernel() {
    int e = blockIdx.x * blockDim.x + threadIdx.x;
    if (e >= E) return;
    unsigned long long p = g_pack[e];
    int s    = (int)(p & 0xffffu);
    int d    = (int)((p >> 16) & 0xffffu);
    int rank = (int)(p >> 32);
    g_csr[g_off[d] + rank] = s;
}

// ---------------------------------------------------------------------------
// GraphConv gather: quarter-warp per edge, bf16 x, fp32 accum
// ---------------------------------------------------------------------------
__global__ __launch_bounds__(256, 6) void gather_nbr_kernel() {
    int gid = blockIdx.x * blockDim.x + threadIdx.x;
    int node = gid >> 5, lane = gid & 31;
    if (node >= N) return;
    int beg = g_off[node], deg = g_deg[node];
    const int q = lane >> 3, l8 = lane & 7;

    float acc[16];
#pragma unroll
    for (int j = 0; j < 16; j++) acc[j] = 0.f;

    int k = q;
    for (; k + 4 < deg; k += 8) {
        int s0 = g_csr[beg + k], s1 = g_csr[beg + k + 4];
        uint4 a0 = *(const uint4*)&g_xb[(size_t)s0 * 64 + l8 * 8];
        uint4 b0 = *(const uint4*)&g_xb[(size_t)s0 * 64 + l8 * 8 + 4];
        uint4 a1 = *(const uint4*)&g_xb[(size_t)s1 * 64 + l8 * 8];
        uint4 b1 = *(const uint4*)&g_xb[(size_t)s1 * 64 + l8 * 8 + 4];
        const uint32_t u0[8] = {a0.x,a0.y,a0.z,a0.w,b0.x,b0.y,b0.z,b0.w};
        const uint32_t u1[8] = {a1.x,a1.y,a1.z,a1.w,b1.x,b1.y,b1.z,b1.w};
#pragma unroll
        for (int j = 0; j < 8; j++) {
            float2 p0 = unpack_bf16(u0[j]), p1 = unpack_bf16(u1[j]);
            acc[j*2]   += p0.x + p1.x;
            acc[j*2+1] += p0.y + p1.y;
        }
    }
    if (k < deg) {
        int s = g_csr[beg + k];
        uint4 a = *(const uint4*)&g_xb[(size_t)s * 64 + l8 * 8];
        uint4 b = *(const uint4*)&g_xb[(size_t)s * 64 + l8 * 8 + 4];
        const uint32_t u[8] = {a.x,a.y,a.z,a.w,b.x,b.y,b.z,b.w};
#pragma unroll
        for (int j = 0; j < 8; j++) {
            float2 p = unpack_bf16(u[j]);
            acc[j*2] += p.x; acc[j*2+1] += p.y;
        }
    }
#pragma unroll
    for (int j = 0; j < 16; j++) {
        acc[j] += __shfl_xor_sync(0xffffffff, acc[j], 8);
        acc[j] += __shfl_xor_sync(0xffffffff, acc[j], 16);
    }
    if (q == 0) {
        float* dst = g_nbr + (size_t)node * 128 + l8 * 16;
#pragma unroll
        for (int j = 0; j < 4; j++)
            *(float4*)(dst + j * 4) = make_float4(acc[j*4], acc[j*4+1], acc[j*4+2], acc[j*4+3]);
    }
}

// ---------------------------------------------------------------------------
// tf32 GEMM. MODE 0: fp32 out + bias + optional ELU.
//           MODE 1: bf16 out + per-head alpha (as1/ad1).
//           MODE 2: bf16 out + single-head alpha partials via atomicAdd.
// ---------------------------------------------------------------------------
template<int BN, int MODE>
__global__ __launch_bounds__(256) void tf32_linear(
    const float* __restrict__ A1, const float* __restrict__ Wa, int K1,
    const float* __restrict__ A2, const float* __restrict__ Wb, int K2,
    const float* __restrict__ bias, void* __restrict__ Cout,
    const float* __restrict__ aS, const float* __restrict__ aD,
    int M, int NCOL, int act)
{
    constexpr int NT = BN / 16;
    __shared__ __align__(16) uint32_t As[4][8][128];
    __shared__ __align__(16) uint32_t Bs[4][BN / 8][64];
    const int tid  = threadIdx.x;
    const int lane = tid & 31, warp = tid >> 5;
    const int wm = warp & 3, wn = warp >> 2;
    const int row0 = blockIdx.x * 128, c0 = blockIdx.y * BN;

    float acc[2][NT][4];
#pragma unroll
    for (int mt = 0; mt < 2; mt++)
#pragma unroll
        for (int nt = 0; nt < NT; nt++)
#pragma unroll
            for (int j = 0; j < 4; j++) acc[mt][nt][j] = 0.f;

    const int nk1 = K1 >> 5;
    const int nk2 = A2 ? (K2 >> 5) : 0;
    for (int t = 0; t < nk1 + nk2; t++) {
        const float* A; const float* W; int K, kb;
        if (t < nk1) { A = A1; W = Wa; K = K1; kb = t << 5; }
        else         { A = A2; W = Wb; K = K2; kb = (t - nk1) << 5; }
        __syncthreads();
#pragma unroll
        for (int i = 0; i < 4; i++) {
            int idx = tid + i * 256;
            int m = idx >> 3, k4 = (idx & 7) << 2;
            float4 v = make_float4(0.f, 0.f, 0.f, 0.f);
            if (row0 + m < M) v = *(const float4*)(A + (size_t)(row0 + m) * K + kb + k4);
            float vv[4] = {v.x, v.y, v.z, v.w};
            int m16 = m >> 4, mm = m & 15, r = mm & 7, rr = mm >> 3;
#pragma unroll
            for (int j = 0; j < 4; j++) {
                int k = k4 + j;
                int reg = ((k & 7) >> 2) * 2 + rr;
                As[k >> 3][m16][(r * 4 + (k & 3)) * 4 + reg] = f2tf32(vv[j]);
            }
        }
#pragma unroll
        for (int i = 0; i < BN / 32; i++) {
            int idx = tid + i * 256;
            int n = idx >> 3, k4 = (idx & 7) << 2;
            float4 v = *(const float4*)(W + (size_t)(c0 + n) * K + kb + k4);
            float vv[4] = {v.x, v.y, v.z, v.w};
            int n8 = n >> 3, nn = n & 7;
#pragma unroll
            for (int j = 0; j < 4; j++) {
                int k = k4 + j;
                Bs[k >> 3][n8][(nn * 4 + (k & 3)) * 2 + ((k & 7) >> 2)] = f2tf32(vv[j]);
            }
        }
        __syncthreads();
#pragma unroll
        for (int k8 = 0; k8 < 4; k8++) {
            uint4 a[2];
            uint2 b[NT];
            a[0] = *(const uint4*)&As[k8][wm * 2 + 0][lane * 4];
            a[1] = *(const uint4*)&As[k8][wm * 2 + 1][lane * 4];
#pragma unroll
            for (int nt = 0; nt < NT; nt++)
                b[nt] = *(const uint2*)&Bs[k8][wn * NT + nt][lane * 2];
#pragma unroll
            for (int mt = 0; mt < 2; mt++)
#pragma unroll
                for (int nt = 0; nt < NT; nt++)
                    mma_tf32(acc[mt][nt], a[mt], b[nt]);
        }
    }

    const int r = lane >> 2, cc = (lane & 3) * 2;
#pragma unroll
    for (int mt = 0; mt < 2; mt++) {
        int row  = row0 + (wm * 2 + mt) * 16 + r;
        int row2 = row + 8;
        float psl = 0.f, pdl = 0.f, psh = 0.f, pdh = 0.f;
#pragma unroll
        for (int nt = 0; nt < NT; nt++) {
            int col = c0 + (wn * NT + nt) * 8 + cc;
            float v0 = acc[mt][nt][0], v1 = acc[mt][nt][1];
            float v2 = acc[mt][nt][2], v3 = acc[mt][nt][3];
            if (MODE == 0) {
                float bx = 0.f, by = 0.f;
                if (bias) { bx = bias[col]; by = bias[col + 1]; }
                float* C = (float*)Cout;
                if (row < M) {
                    float a0 = v0 + bx, a1 = v1 + by;
                    if (act == 1) { a0 = elu1(a0); a1 = elu1(a1); }
                    *(float2*)(C + (size_t)row * NCOL + col) = make_float2(a0, a1);
                }
                if (row2 < M) {
                    float a2 = v2 + bx, a3 = v3 + by;
                    if (act == 1) { a2 = elu1(a2); a3 = elu1(a3); }
                    *(float2*)(C + (size_t)row2 * NCOL + col) = make_float2(a2, a3);
                }
            } else {
                uint32_t* Zb = (uint32_t*)Cout;
                if (row  < M) Zb[(size_t)row  * 32 + (col >> 1)] = pack_bf16(v0, v1);
                if (row2 < M) Zb[(size_t)row2 * 32 + (col >> 1)] = pack_bf16(v2, v3);
                float s0 = aS[col], s1 = aS[col + 1];
                float d0 = aD[col], d1 = aD[col + 1];
                if (MODE == 1) {
                    int h = wn * NT + nt;
                    float ps_lo = v0 * s0 + v1 * s1;
                    float pd_lo = v0 * d0 + v1 * d1;
                    float ps_hi = v2 * s0 + v3 * s1;
                    float pd_hi = v2 * d0 + v3 * d1;
                    ps_lo += __shfl_xor_sync(0xffffffff, ps_lo, 1);
                    ps_lo += __shfl_xor_sync(0xffffffff, ps_lo, 2);
                    pd_lo += __shfl_xor_sync(0xffffffff, pd_lo, 1);
                    pd_lo += __shfl_xor_sync(0xffffffff, pd_lo, 2);
                    ps_hi += __shfl_xor_sync(0xffffffff, ps_hi, 1);
                    ps_hi += __shfl_xor_sync(0xffffffff, ps_hi, 2);
                    pd_hi += __shfl_xor_sync(0xffffffff, pd_hi, 1);
                    pd_hi += __shfl_xor_sync(0xffffffff, pd_hi, 2);
                    if ((lane & 3) == 0) {
                        if (row  < M) { g_as1[(size_t)row  * 8 + h] = ps_lo; g_ad1[(size_t)row  * 8 + h] = pd_lo; }
                        if (row2 < M) { g_as1[(size_t)row2 * 8 + h] = ps_hi; g_ad1[(size_t)row2 * 8 + h] = pd_hi; }
                    }
                } else {
                    psl += v0 * s0 + v1 * s1;
                    pdl += v0 * d0 + v1 * d1;
                    psh += v2 * s0 + v3 * s1;
                    pdh += v2 * d0 + v3 * d1;
                }
            }
        }
        if (MODE == 2) {
            psl += __shfl_xor_sync(0xffffffff, psl, 1);
            psl += __shfl_xor_sync(0xffffffff, psl, 2);
            pdl += __shfl_xor_sync(0xffffffff, pdl, 1);
            pdl += __shfl_xor_sync(0xffffffff, pdl, 2);
            psh += __shfl_xor_sync(0xffffffff, psh, 1);
            psh += __shfl_xor_sync(0xffffffff, psh, 2);
            pdh += __shfl_xor_sync(0xffffffff, pdh, 1);
            pdh += __shfl_xor_sync(0xffffffff, pdh, 2);
            if ((lane & 3) == 0) {
                if (row  < M) { atomicAdd(&g_as2[row],  psl); atomicAdd(&g_ad2[row],  pdl); }
                if (row2 < M) { atomicAdd(&g_as2[row2], psh); atomicAdd(&g_ad2[row2], pdh); }
            }
        }
    }
}

// ---------------------------------------------------------------------------
// GAT1 fused: quarter-warp per edge (2 edges in flight), bf16 z
// ---------------------------------------------------------------------------
__global__ void gat1_fused(const float* __restrict__ b1) {
    int gid = blockIdx.x * blockDim.x + threadIdx.x;
    int node = gid >> 5, lane = gid & 31;
    if (node >= N) return;
    int beg = g_off[node], deg = g_deg[node];
    const int q = lane >> 3, l8 = lane & 7;
    const float adh = g_ad1[(size_t)node * 8 + l8];

    float acc[8];
#pragma unroll
    for (int j = 0; j < 8; j++) acc[j] = 0.f;
    float den = 0.f;

    if (q == 0) {  // self-loop
        float w = __expf(lrelu(g_as1[(size_t)node * 8 + l8] + adh));
        uint4 u = *(const uint4*)&g_z1b[(size_t)node * 32 + l8 * 4];
        const uint32_t uu[4] = {u.x, u.y, u.z, u.w};
#pragma unroll
        for (int j = 0; j < 4; j++) {
            float2 p = unpack_bf16(uu[j]);
            acc[j*2] = w * p.x; acc[j*2+1] = w * p.y;
        }
        den = w;
    }
    int k = q;
    for (; k + 4 < deg; k += 8) {
        int s0 = g_csr[beg + k], s1 = g_csr[beg + k + 4];
        float w0 = __expf(lrelu(g_as1[(size_t)s0 * 8 + l8] + adh));
        float w1 = __expf(lrelu(g_as1[(size_t)s1 * 8 + l8] + adh));
        uint4 u0 = *(const uint4*)&g_z1b[(size_t)s0 * 32 + l8 * 4];
        uint4 u1 = *(const uint4*)&g_z1b[(size_t)s1 * 32 + l8 * 4];
        const uint32_t a0[4] = {u0.x, u0.y, u0.z, u0.w};
        const uint32_t a1[4] = {u1.x, u1.y, u1.z, u1.w};
#pragma unroll
        for (int j = 0; j < 4; j++) {
            float2 p0 = unpack_bf16(a0[j]), p1 = unpack_bf16(a1[j]);
            acc[j*2]   += w0 * p0.x + w1 * p1.x;
            acc[j*2+1] += w0 * p0.y + w1 * p1.y;
        }
        den += w0 + w1;
    }
    if (k < deg) {
        int s = g_csr[beg + k];
        float w = __expf(lrelu(g_as1[(size_t)s * 8 + l8] + adh));
        uint4 u = *(const uint4*)&g_z1b[(size_t)s * 32 + l8 * 4];
        const uint32_t uu[4] = {u.x, u.y, u.z, u.w};
#pragma unroll
        for (int j = 0; j < 4; j++) {
            float2 p = unpack_bf16(uu[j]);
            acc[j*2] += w * p.x; acc[j*2+1] += w * p.y;
        }
        den += w;
    }
#pragma unroll
    for (int j = 0; j < 8; j++) {
        acc[j] += __shfl_xor_sync(0xffffffff, acc[j], 8);
        acc[j] += __shfl_xor_sync(0xffffffff, acc[j], 16);
    }
    den += __shfl_xor_sync(0xffffffff, den, 8);
    den += __shfl_xor_sync(0xffffffff, den, 16);
    if (q == 0) {
        float rh = 1.f / (den + 1e-16f);
        float* dst = g_h2 + (size_t)node * 64 + l8 * 8;
        const float* bb = b1 + l8 * 8;
#pragma unroll
        for (int j = 0; j < 2; j++) {
            float4 bv = *(const float4*)(bb + j * 4);
            *(float4*)(dst + j * 4) = make_float4(
                elu1(acc[j*4]   * rh + bv.x), elu1(acc[j*4+1] * rh + bv.y),
                elu1(acc[j*4+2] * rh + bv.z), elu1(acc[j*4+3] * rh + bv.w));
        }
    }
}

// ---------------------------------------------------------------------------
// GAT2 fused + regression head (quarter-warp per edge)
// ---------------------------------------------------------------------------
__global__ void gat2_fused(const float* __restrict__ Wr) {
    __shared__ float bp[8];
    int gid = blockIdx.x * blockDim.x + threadIdx.x;
    int node = gid >> 5, lane = gid & 31, wid = threadIdx.x >> 5;
    int beg = g_off[node], deg = g_deg[node];
    const int q = lane >> 3, l8 = lane & 7;
    const float adn = g_ad2[node];

    float acc[8];
#pragma unroll
    for (int j = 0; j < 8; j++) acc[j] = 0.f;
    float den = 0.f;

    if (q == 0) {
        float w = __expf(lrelu(g_as2[node] + adn));
        uint4 u = *(const uint4*)&g_z2b[(size_t)node * 32 + l8 * 4];
        const uint32_t uu[4] = {u.x, u.y, u.z, u.w};
#pragma unroll
        for (int j = 0; j < 4; j++) {
            float2 p = unpack_bf16(uu[j]);
            acc[j*2] = w * p.x; acc[j*2+1] = w * p.y;
        }
        den = w;
    }
    int k = q;
    for (; k + 4 < deg; k += 8) {
        int s0 = g_csr[beg + k], s1 = g_csr[beg + k + 4];
        float w0 = __expf(lrelu(g_as2[s0] + adn));
        float w1 = __expf(lrelu(g_as2[s1] + adn));
        uint4 u0 = *(const uint4*)&g_z2b[(size_t)s0 * 32 + l8 * 4];
        uint4 u1 = *(const uint4*)&g_z2b[(size_t)s1 * 32 + l8 * 4];
        const uint32_t a0[4] = {u0.x, u0.y, u0.z, u0.w};
        const uint32_t a1[4] = {u1.x, u1.y, u1.z, u1.w};
#pragma unroll
        for (int j = 0; j < 4; j++) {
            float2 p0 = unpack_bf16(a0[j]), p1 = unpack_bf16(a1[j]);
            acc[j*2]   += w0 * p0.x + w1 * p1.x;
            acc[j*2+1] += w0 * p0.y + w1 * p1.y;
        }
        den += w0 + w1;
    }
    if (k < deg) {
        int s = g_csr[beg + k];
        float w = __expf(lrelu(g_as2[s] + adn));
        uint4 u = *(const uint4*)&g_z2b[(size_t)s * 32 + l8 * 4];
        const uint32_t uu[4] = {u.x, u.y, u.z, u.w};
#pragma unroll
        for (int j = 0; j < 4; j++) {
            float2 p = unpack_bf16(uu[j]);
            acc[j*2] += w * p.x; acc[j*2+1] += w * p.y;
        }
        den += w;
    }
#pragma unroll
    for (int j = 0; j < 8; j++) {
        acc[j] += __shfl_xor_sync(0xffffffff, acc[j], 8);
        acc[j] += __shfl_xor_sync(0xffffffff, acc[j], 16);
    }
    den += __shfl_xor_sync(0xffffffff, den, 8);
    den += __shfl_xor_sync(0xffffffff, den, 16);

    float pd = 0.f;
    const float* wp = Wr + l8 * 8;
#pragma unroll
    for (int j = 0; j < 8; j++) pd += acc[j] * wp[j];
    pd += __shfl_xor_sync(0xffffffff, pd, 1);
    pd += __shfl_xor_sync(0xffffffff, pd, 2);
    pd += __shfl_xor_sync(0xffffffff, pd, 4);
    if (lane == 0) bp[wid] = pd / (den + 1e-16f);
    __syncthreads();
    if (threadIdx.x == 0) {
        float s = 0.f;
#pragma unroll
        for (int j = 0; j < 8; j++) s += bp[j];
        atomicAdd(&g_out_acc, s);
    }
}

// ---------------------------------------------------------------------------
// final: out = acc/N + dot(b2, Wr) + br
// ---------------------------------------------------------------------------
__global__ void final_kernel(const float* __restrict__ Wr, const float* __restrict__ br,
                             const float* __restrict__ b2, float* __restrict__ out) {
    __shared__ float sm[64];
    int t = threadIdx.x;
    sm[t] = b2[t] * Wr[t];
    __syncthreads();
    if (t == 0) {
        float s = 0.f;
        for (int i = 0; i < 64; i++) s += sm[i];
        out[0] = g_out_acc * (1.0f / (float)N) + s + br[0];
    }
}

// ---------------------------------------------------------------------------
// Launch
// ---------------------------------------------------------------------------
extern "C" void kernel_launch(void* const* d_in, const int* in_sizes, int n_in,
                              void* d_out, int out_size) {
    const float* x      = (const float*)d_in[0];
    const void*  ei     = d_in[1];
    const float* W_rel  = (const float*)d_in[2];
    const float* b_rel  = (const float*)d_in[3];
    const float* W_root = (const float*)d_in[4];
    const float* W1     = (const float*)d_in[5];
    const float* a1s    = (const float*)d_in[6];
    const float* a1d    = (const float*)d_in[7];
    const float* b1     = (const float*)d_in[8];
    const float* W2     = (const float*)d_in[9];
    const float* a2s    = (const float*)d_in[10];
    const float* a2d    = (const float*)d_in[11];
    const float* b2     = (const float*)d_in[12];
    const float* Wr     = (const float*)d_in[13];
    const float* br     = (const float*)d_in[14];
    float* out          = (float*)d_out;

    float *p_nbr, *p_h, *p_h2;
    void *p_z1b, *p_z2b;
    cudaGetSymbolAddress((void**)&p_nbr, g_nbr);
    cudaGetSymbolAddress((void**)&p_h,   g_h);
    cudaGetSymbolAddress(&p_z1b, g_z1b);
    cudaGetSymbolAddress((void**)&p_h2,  g_h2);
    cudaGetSymbolAddress(&p_z2b, g_z2b);

    init_kernel<<<256, 256>>>((const int*)ei, x);

    hist_kernel<<<(E + 255) / 256, 256>>>(ei);
    scan_kernel<<<1, 1024>>>();
    fill_kernel<<<(E + 255) / 256, 256>>>();

    gather_nbr_kernel<<<(N * 32 + 255) / 256, 256>>>();
    {
        dim3 g((N + 127) / 128, 1);
        tf32_linear<128, 0><<<g, 256>>>(p_nbr, W_rel, 128, x, W_root, 128,
                                        b_rel, p_h, nullptr, nullptr, N, 128, 1);
    }
    {
        dim3 g((N + 127) / 128, 1);
        tf32_linear<64, 1><<<g, 256>>>(p_h, W1, 128, nullptr, nullptr, 0,
                                       nullptr, p_z1b, a1s, a1d, N, 64, 0);
    }
    gat1_fused<<<(N * 32 + 255) / 256, 256>>>(b1);

    {
        dim3 g((N + 127) / 128, 1);
        tf32_linear<64, 2><<<g, 256>>>(p_h2, W2, 64, nullptr, nullptr, 0,
                                       nullptr, p_z2b, a2s, a2d, N, 64, 0);
    }
    gat2_fused<<<N * 32 / 256, 256>>>(Wr);

    final_kernel<<<1, 64>>>(Wr, br, b2, out);
}

// round 11
// speedup vs baseline: 1.1488x; 1.1089x over previous
#include <cuda_runtime.h>
#include <cuda_bf16.h>
#include <math.h>
#include <stdint.h>

constexpr int N = 50000;
constexpr int E = 800000;

// ---------------------------------------------------------------------------
// Device scratch
// ---------------------------------------------------------------------------
__device__ __align__(16) uint32_t g_xb [N * 64];   // x as bf16x2 (128 ch)
__device__ __align__(16) float g_nbr[N * 128];
__device__ __align__(16) float g_h  [N * 128];
__device__ __align__(16) uint32_t g_z1b[N * 32];   // z1 as bf16x2 (64 ch)
__device__ __align__(16) uint32_t g_z2b[N * 32];   // z2 as bf16x2
__device__ __align__(16) float g_as1[N * 8];
__device__ __align__(16) float g_ad1[N * 8];
__device__ __align__(16) float g_h2 [N * 64];
__device__ float g_as2[N];
__device__ float g_ad2[N];
__device__ float g_out_acc;          // reset by gat2 last block
__device__ unsigned g_done;          // reset by gat2 last block
__device__ int g_deg[N];
__device__ int g_off[N];
__device__ unsigned long long g_pack[E];
__device__ int g_csr[E];
__device__ int g_is64;

// ---------------------------------------------------------------------------
// Helpers
// ---------------------------------------------------------------------------
__device__ __forceinline__ float lrelu(float x) { return x > 0.f ? x : 0.2f * x; }
__device__ __forceinline__ float elu1(float x)  { return x > 0.f ? x : __expf(x) - 1.f; }

__device__ __forceinline__ uint32_t pack_bf16(float a, float b) {
    __nv_bfloat162 v = __float22bfloat162_rn(make_float2(a, b));
    return *reinterpret_cast<uint32_t*>(&v);
}
__device__ __forceinline__ float2 unpack_bf16(uint32_t u) {
    return __bfloat1622float2(*reinterpret_cast<__nv_bfloat162*>(&u));
}

// m16n8k16 bf16 MMA, fp32 accumulate
__device__ __forceinline__ void mma_bf16(float c[4], const uint4& a, const uint2& b) {
    asm volatile(
        "mma.sync.aligned.m16n8k16.row.col.f32.bf16.bf16.f32 "
        "{%0,%1,%2,%3}, {%4,%5,%6,%7}, {%8,%9}, {%0,%1,%2,%3};"
        : "+f"(c[0]), "+f"(c[1]), "+f"(c[2]), "+f"(c[3])
        : "r"(a.x), "r"(a.y), "r"(a.z), "r"(a.w), "r"(b.x), "r"(b.y));
}

__device__ __forceinline__ int edge_id(const void* ei, long long idx) {
    return g_is64 ? (int)((const long long*)ei)[idx] : ((const int*)ei)[idx];
}
__device__ __forceinline__ int edge_src(const void* ei, int e) { return edge_id(ei, e); }
__device__ __forceinline__ int edge_dst(const void* ei, int e) { return edge_id(ei, (long long)E + e); }

// ---------------------------------------------------------------------------
// init: zero counters, convert x -> bf16, dtype detect (block 0)
// ---------------------------------------------------------------------------
__global__ void init_kernel(const int* ei, const float* __restrict__ x) {
    int i = blockIdx.x * blockDim.x + threadIdx.x;
    int stride = gridDim.x * blockDim.x;
    for (int t = i; t < N; t += stride) { g_deg[t] = 0; g_as2[t] = 0.f; g_ad2[t] = 0.f; }
    for (int t = i; t < N * 64; t += stride) {
        float2 v = ((const float2*)x)[t];
        g_xb[t] = pack_bf16(v.x, v.y);
    }
    if (blockIdx.x == 0) {
        __shared__ int any;
        if (threadIdx.x == 0) any = 0;
        __syncthreads();
        for (int t = threadIdx.x; t < 1024; t += blockDim.x)
            if (ei[2 * t + 1] != 0) atomicOr(&any, 1);
        __syncthreads();
        if (threadIdx.x == 0) g_is64 = any ? 0 : 1;
    }
}

// ---------------------------------------------------------------------------
// CSR build
// ---------------------------------------------------------------------------
__global__ void hist_kernel(const void* __restrict__ ei) {
    int e = blockIdx.x * blockDim.x + threadIdx.x;
    if (e >= E) return;
    int s = edge_src(ei, e), d = edge_dst(ei, e);
    unsigned rank = atomicAdd(&g_deg[d], 1);
    g_pack[e] = (unsigned long long)(unsigned)s
              | ((unsigned long long)(unsigned)d << 16)
              | ((unsigned long long)rank << 32);
}

__global__ void scan_kernel() {
    __shared__ int wsum[32];
    __shared__ int s_carry;
    int tid = threadIdx.x, lane = tid & 31, wid = tid >> 5;
    if (tid == 0) s_carry = 0;
    __syncthreads();
    for (int base = 0; base < N; base += 1024) {
        int i = base + tid;
        int v = (i < N) ? g_deg[i] : 0;
        int s = v;
#pragma unroll
        for (int o = 1; o < 32; o <<= 1) {
            int u = __shfl_up_sync(0xffffffff, s, o);
            if (lane >= o) s += u;
        }
        if (lane == 31) wsum[wid] = s;
        __syncthreads();
        if (wid == 0) {
            int w = wsum[lane];
#pragma unroll
            for (int o = 1; o < 32; o <<= 1) {
                int u = __shfl_up_sync(0xffffffff, w, o);
                if (lane >= o) w += u;
            }
            wsum[lane] = w;
        }
        __syncthreads();
        int prev = (wid > 0) ? wsum[wid - 1] : 0;
        int carry = s_carry;
        if (i < N) g_off[i] = carry + prev + s - v;
        __syncthreads();
        if (tid == 1023) s_carry = carry + wsum[31];
        __syncthreads();
    }
}

// fill: 2 edges per thread, one 16B pack load
__global__ void fill_kernel() {
    int e = (blockIdx.x * blockDim.x + threadIdx.x) * 2;
    if (e >= E) return;
    ulonglong2 pp = *(const ulonglong2*)&g_pack[e];
    {
        unsigned long long p = pp.x;
        g_csr[g_off[(int)((p >> 16) & 0xffffu)] + (int)(p >> 32)] = (int)(p & 0xffffu);
    }
    {
        unsigned long long p = pp.y;
        g_csr[g_off[(int)((p >> 16) & 0xffffu)] + (int)(p >> 32)] = (int)(p & 0xffffu);
    }
}

// ---------------------------------------------------------------------------
// GraphConv gather: quarter-warp per edge, bf16 x, fp32 accum
// ---------------------------------------------------------------------------
__global__ __launch_bounds__(256, 6) void gather_nbr_kernel() {
    int gid = blockIdx.x * blockDim.x + threadIdx.x;
    int node = gid >> 5, lane = gid & 31;
    if (node >= N) return;
    int beg = g_off[node], deg = g_deg[node];
    const int q = lane >> 3, l8 = lane & 7;

    float acc[16];
#pragma unroll
    for (int j = 0; j < 16; j++) acc[j] = 0.f;

    int k = q;
    for (; k + 4 < deg; k += 8) {
        int s0 = g_csr[beg + k], s1 = g_csr[beg + k + 4];
        uint4 a0 = *(const uint4*)&g_xb[(size_t)s0 * 64 + l8 * 8];
        uint4 b0 = *(const uint4*)&g_xb[(size_t)s0 * 64 + l8 * 8 + 4];
        uint4 a1 = *(const uint4*)&g_xb[(size_t)s1 * 64 + l8 * 8];
        uint4 b1 = *(const uint4*)&g_xb[(size_t)s1 * 64 + l8 * 8 + 4];
        const uint32_t u0[8] = {a0.x,a0.y,a0.z,a0.w,b0.x,b0.y,b0.z,b0.w};
        const uint32_t u1[8] = {a1.x,a1.y,a1.z,a1.w,b1.x,b1.y,b1.z,b1.w};
#pragma unroll
        for (int j = 0; j < 8; j++) {
            float2 p0 = unpack_bf16(u0[j]), p1 = unpack_bf16(u1[j]);
            acc[j*2]   += p0.x + p1.x;
            acc[j*2+1] += p0.y + p1.y;
        }
    }
    if (k < deg) {
        int s = g_csr[beg + k];
        uint4 a = *(const uint4*)&g_xb[(size_t)s * 64 + l8 * 8];
        uint4 b = *(const uint4*)&g_xb[(size_t)s * 64 + l8 * 8 + 4];
        const uint32_t u[8] = {a.x,a.y,a.z,a.w,b.x,b.y,b.z,b.w};
#pragma unroll
        for (int j = 0; j < 8; j++) {
            float2 p = unpack_bf16(u[j]);
            acc[j*2] += p.x; acc[j*2+1] += p.y;
        }
    }
#pragma unroll
    for (int j = 0; j < 16; j++) {
        acc[j] += __shfl_xor_sync(0xffffffff, acc[j], 8);
        acc[j] += __shfl_xor_sync(0xffffffff, acc[j], 16);
    }
    if (q == 0) {
        float* dst = g_nbr + (size_t)node * 128 + l8 * 16;
#pragma unroll
        for (int j = 0; j < 4; j++)
            *(float4*)(dst + j * 4) = make_float4(acc[j*4], acc[j*4+1], acc[j*4+2], acc[j*4+3]);
    }
}

// ---------------------------------------------------------------------------
// bf16 GEMM (m16n8k16). MODE 0: fp32 out + bias + optional ELU.
//   MODE 1: bf16 out + per-head alpha (as1/ad1).
//   MODE 2: bf16 out + single-head alpha partials via atomicAdd.
// A row-major [M,K] fp32, W row-major [NCOL,K] fp32; staged as bf16x2
// fragments. BM=128, BK=32 (2 k16 slabs per chunk), 256 threads.
// ---------------------------------------------------------------------------
template<int BN, int MODE>
__global__ __launch_bounds__(256) void bf16_linear(
    const float* __restrict__ A1, const float* __restrict__ Wa, int K1,
    const float* __restrict__ A2, const float* __restrict__ Wb, int K2,
    const float* __restrict__ bias, void* __restrict__ Cout,
    const float* __restrict__ aS, const float* __restrict__ aD,
    int M, int NCOL, int act)
{
    constexpr int NT = BN / 16;
    __shared__ __align__(16) uint32_t As[2][8][128];       // [k16][m16][lane*4+reg] 8KB
    __shared__ __align__(16) uint32_t Bs[2][BN / 8][64];   // [k16][n8][lane*2+reg]
    const int tid  = threadIdx.x;
    const int lane = tid & 31, warp = tid >> 5;
    const int wm = warp & 3, wn = warp >> 2;
    const int row0 = blockIdx.x * 128, c0 = blockIdx.y * BN;

    float acc[2][NT][4];
#pragma unroll
    for (int mt = 0; mt < 2; mt++)
#pragma unroll
        for (int nt = 0; nt < NT; nt++)
#pragma unroll
            for (int j = 0; j < 4; j++) acc[mt][nt][j] = 0.f;

    const int nk1 = K1 >> 5;
    const int nk2 = A2 ? (K2 >> 5) : 0;
    for (int t = 0; t < nk1 + nk2; t++) {
        const float* A; const float* W; int K, kb;
        if (t < nk1) { A = A1; W = Wa; K = K1; kb = t << 5; }
        else         { A = A2; W = Wb; K = K2; kb = (t - nk1) << 5; }
        __syncthreads();
        // stage A tile 128x32 -> bf16x2 fragment order
#pragma unroll
        for (int i = 0; i < 4; i++) {
            int idx = tid + i * 256;
            int m = idx >> 3, k4 = (idx & 7) << 2;
            float4 v = make_float4(0.f, 0.f, 0.f, 0.f);
            if (row0 + m < M) v = *(const float4*)(A + (size_t)(row0 + m) * K + kb + k4);
            uint32_t pair0 = pack_bf16(v.x, v.y);
            uint32_t pair1 = pack_bf16(v.z, v.w);
            int m16 = m >> 4, mm = m & 15, r = mm & 7, rr = mm >> 3;
            int slab = k4 >> 4, kk = k4 & 15;
            int c0l = (kk >> 1) & 3;
            int reg = rr + 2 * ((kk >> 3) & 1);
            As[slab][m16][(r * 4 + c0l) * 4 + reg]     = pair0;
            As[slab][m16][(r * 4 + c0l + 1) * 4 + reg] = pair1;
        }
        // stage W tile BNx32 -> bf16x2 fragment order
#pragma unroll
        for (int i = 0; i < BN / 32; i++) {
            int idx = tid + i * 256;
            int n = idx >> 3, k4 = (idx & 7) << 2;
            float4 v = *(const float4*)(W + (size_t)(c0 + n) * K + kb + k4);
            uint32_t pair0 = pack_bf16(v.x, v.y);
            uint32_t pair1 = pack_bf16(v.z, v.w);
            int n8 = n >> 3, nn = n & 7;
            int slab = k4 >> 4, kk = k4 & 15;
            int c0l = (kk >> 1) & 3;
            int reg = (kk >> 3) & 1;
            Bs[slab][n8][(nn * 4 + c0l) * 2 + reg]     = pair0;
            Bs[slab][n8][(nn * 4 + c0l + 1) * 2 + reg] = pair1;
        }
        __syncthreads();
#pragma unroll
        for (int k16 = 0; k16 < 2; k16++) {
            uint4 a[2];
            uint2 b[NT];
            a[0] = *(const uint4*)&As[k16][wm * 2 + 0][lane * 4];
            a[1] = *(const uint4*)&As[k16][wm * 2 + 1][lane * 4];
#pragma unroll
            for (int nt = 0; nt < NT; nt++)
                b[nt] = *(const uint2*)&Bs[k16][wn * NT + nt][lane * 2];
#pragma unroll
            for (int mt = 0; mt < 2; mt++)
#pragma unroll
                for (int nt = 0; nt < NT; nt++)
                    mma_bf16(acc[mt][nt], a[mt], b[nt]);
        }
    }

    const int r = lane >> 2, cc = (lane & 3) * 2;
#pragma unroll
    for (int mt = 0; mt < 2; mt++) {
        int row  = row0 + (wm * 2 + mt) * 16 + r;
        int row2 = row + 8;
        float psl = 0.f, pdl = 0.f, psh = 0.f, pdh = 0.f;
#pragma unroll
        for (int nt = 0; nt < NT; nt++) {
            int col = c0 + (wn * NT + nt) * 8 + cc;
            float v0 = acc[mt][nt][0], v1 = acc[mt][nt][1];
            float v2 = acc[mt][nt][2], v3 = acc[mt][nt][3];
            if (MODE == 0) {
                float bx = 0.f, by = 0.f;
                if (bias) { bx = bias[col]; by = bias[col + 1]; }
                float* C = (float*)Cout;
                if (row < M) {
                    float a0 = v0 + bx, a1 = v1 + by;
                    if (act == 1) { a0 = elu1(a0); a1 = elu1(a1); }
                    *(float2*)(C + (size_t)row * NCOL + col) = make_float2(a0, a1);
                }
                if (row2 < M) {
                    float a2 = v2 + bx, a3 = v3 + by;
                    if (act == 1) { a2 = elu1(a2); a3 = elu1(a3); }
                    *(float2*)(C + (size_t)row2 * NCOL + col) = make_float2(a2, a3);
                }
            } else {
                uint32_t* Zb = (uint32_t*)Cout;
                if (row  < M) Zb[(size_t)row  * 32 + (col >> 1)] = pack_bf16(v0, v1);
                if (row2 < M) Zb[(size_t)row2 * 32 + (col >> 1)] = pack_bf16(v2, v3);
                float s0 = aS[col], s1 = aS[col + 1];
                float d0 = aD[col], d1 = aD[col + 1];
                if (MODE == 1) {
                    int h = wn * NT + nt;
                    float ps_lo = v0 * s0 + v1 * s1;
                    float pd_lo = v0 * d0 + v1 * d1;
                    float ps_hi = v2 * s0 + v3 * s1;
                    float pd_hi = v2 * d0 + v3 * d1;
                    ps_lo += __shfl_xor_sync(0xffffffff, ps_lo, 1);
                    ps_lo += __shfl_xor_sync(0xffffffff, ps_lo, 2);
                    pd_lo += __shfl_xor_sync(0xffffffff, pd_lo, 1);
                    pd_lo += __shfl_xor_sync(0xffffffff, pd_lo, 2);
                    ps_hi += __shfl_xor_sync(0xffffffff, ps_hi, 1);
                    ps_hi += __shfl_xor_sync(0xffffffff, ps_hi, 2);
                    pd_hi += __shfl_xor_sync(0xffffffff, pd_hi, 1);
                    pd_hi += __shfl_xor_sync(0xffffffff, pd_hi, 2);
                    if ((lane & 3) == 0) {
                        if (row  < M) { g_as1[(size_t)row  * 8 + h] = ps_lo; g_ad1[(size_t)row  * 8 + h] = pd_lo; }
                        if (row2 < M) { g_as1[(size_t)row2 * 8 + h] = ps_hi; g_ad1[(size_t)row2 * 8 + h] = pd_hi; }
                    }
                } else {
                    psl += v0 * s0 + v1 * s1;
                    pdl += v0 * d0 + v1 * d1;
                    psh += v2 * s0 + v3 * s1;
                    pdh += v2 * d0 + v3 * d1;
                }
            }
        }
        if (MODE == 2) {
            psl += __shfl_xor_sync(0xffffffff, psl, 1);
            psl += __shfl_xor_sync(0xffffffff, psl, 2);
            pdl += __shfl_xor_sync(0xffffffff, pdl, 1);
            pdl += __shfl_xor_sync(0xffffffff, pdl, 2);
            psh += __shfl_xor_sync(0xffffffff, psh, 1);
            psh += __shfl_xor_sync(0xffffffff, psh, 2);
            pdh += __shfl_xor_sync(0xffffffff, pdh, 1);
            pdh += __shfl_xor_sync(0xffffffff, pdh, 2);
            if ((lane & 3) == 0) {
                if (row  < M) { atomicAdd(&g_as2[row],  psl); atomicAdd(&g_ad2[row],  pdl); }
                if (row2 < M) { atomicAdd(&g_as2[row2], psh); atomicAdd(&g_ad2[row2], pdh); }
            }
        }
    }
}

// ---------------------------------------------------------------------------
// GAT1 fused: quarter-warp per edge (2 edges in flight), bf16 z
// ---------------------------------------------------------------------------
__global__ void gat1_fused(const float* __restrict__ b1) {
    int gid = blockIdx.x * blockDim.x + threadIdx.x;
    int node = gid >> 5, lane = gid & 31;
    if (node >= N) return;
    int beg = g_off[node], deg = g_deg[node];
    const int q = lane >> 3, l8 = lane & 7;
    const float adh = g_ad1[(size_t)node * 8 + l8];

    float acc[8];
#pragma unroll
    for (int j = 0; j < 8; j++) acc[j] = 0.f;
    float den = 0.f;

    if (q == 0) {  // self-loop
        float w = __expf(lrelu(g_as1[(size_t)node * 8 + l8] + adh));
        uint4 u = *(const uint4*)&g_z1b[(size_t)node * 32 + l8 * 4];
        const uint32_t uu[4] = {u.x, u.y, u.z, u.w};
#pragma unroll
        for (int j = 0; j < 4; j++) {
            float2 p = unpack_bf16(uu[j]);
            acc[j*2] = w * p.x; acc[j*2+1] = w * p.y;
        }
        den = w;
    }
    int k = q;
    for (; k + 4 < deg; k += 8) {
        int s0 = g_csr[beg + k], s1 = g_csr[beg + k + 4];
        float w0 = __expf(lrelu(g_as1[(size_t)s0 * 8 + l8] + adh));
        float w1 = __expf(lrelu(g_as1[(size_t)s1 * 8 + l8] + adh));
        uint4 u0 = *(const uint4*)&g_z1b[(size_t)s0 * 32 + l8 * 4];
        uint4 u1 = *(const uint4*)&g_z1b[(size_t)s1 * 32 + l8 * 4];
        const uint32_t a0[4] = {u0.x, u0.y, u0.z, u0.w};
        const uint32_t a1[4] = {u1.x, u1.y, u1.z, u1.w};
#pragma unroll
        for (int j = 0; j < 4; j++) {
            float2 p0 = unpack_bf16(a0[j]), p1 = unpack_bf16(a1[j]);
            acc[j*2]   += w0 * p0.x + w1 * p1.x;
            acc[j*2+1] += w0 * p0.y + w1 * p1.y;
        }
        den += w0 + w1;
    }
    if (k < deg) {
        int s = g_csr[beg + k];
        float w = __expf(lrelu(g_as1[(size_t)s * 8 + l8] + adh));
        uint4 u = *(const uint4*)&g_z1b[(size_t)s * 32 + l8 * 4];
        const uint32_t uu[4] = {u.x, u.y, u.z, u.w};
#pragma unroll
        for (int j = 0; j < 4; j++) {
            float2 p = unpack_bf16(uu[j]);
            acc[j*2] += w * p.x; acc[j*2+1] += w * p.y;
        }
        den += w;
    }
#pragma unroll
    for (int j = 0; j < 8; j++) {
        acc[j] += __shfl_xor_sync(0xffffffff, acc[j], 8);
        acc[j] += __shfl_xor_sync(0xffffffff, acc[j], 16);
    }
    den += __shfl_xor_sync(0xffffffff, den, 8);
    den += __shfl_xor_sync(0xffffffff, den, 16);
    if (q == 0) {
        float rh = 1.f / (den + 1e-16f);
        float* dst = g_h2 + (size_t)node * 64 + l8 * 8;
        const float* bb = b1 + l8 * 8;
#pragma unroll
        for (int j = 0; j < 2; j++) {
            float4 bv = *(const float4*)(bb + j * 4);
            *(float4*)(dst + j * 4) = make_float4(
                elu1(acc[j*4]   * rh + bv.x), elu1(acc[j*4+1] * rh + bv.y),
                elu1(acc[j*4+2] * rh + bv.z), elu1(acc[j*4+3] * rh + bv.w));
        }
    }
}

// ---------------------------------------------------------------------------
// GAT2 fused + regression head; last block writes the final output
// ---------------------------------------------------------------------------
__global__ void gat2_fused(const float* __restrict__ Wr, const float* __restrict__ br,
                           const float* __restrict__ b2, float* __restrict__ out) {
    __shared__ float bp[8];
    int gid = blockIdx.x * blockDim.x + threadIdx.x;
    int node = gid >> 5, lane = gid & 31, wid = threadIdx.x >> 5;
    int beg = g_off[node], deg = g_deg[node];
    const int q = lane >> 3, l8 = lane & 7;
    const float adn = g_ad2[node];

    float acc[8];
#pragma unroll
    for (int j = 0; j < 8; j++) acc[j] = 0.f;
    float den = 0.f;

    if (q == 0) {
        float w = __expf(lrelu(g_as2[node] + adn));
        uint4 u = *(const uint4*)&g_z2b[(size_t)node * 32 + l8 * 4];
        const uint32_t uu[4] = {u.x, u.y, u.z, u.w};
#pragma unroll
        for (int j = 0; j < 4; j++) {
            float2 p = unpack_bf16(uu[j]);
            acc[j*2] = w * p.x; acc[j*2+1] = w * p.y;
        }
        den = w;
    }
    int k = q;
    for (; k + 4 < deg; k += 8) {
        int s0 = g_csr[beg + k], s1 = g_csr[beg + k + 4];
        float w0 = __expf(lrelu(g_as2[s0] + adn));
        float w1 = __expf(lrelu(g_as2[s1] + adn));
        uint4 u0 = *(const uint4*)&g_z2b[(size_t)s0 * 32 + l8 * 4];
        uint4 u1 = *(const uint4*)&g_z2b[(size_t)s1 * 32 + l8 * 4];
        const uint32_t a0[4] = {u0.x, u0.y, u0.z, u0.w};
        const uint32_t a1[4] = {u1.x, u1.y, u1.z, u1.w};
#pragma unroll
        for (int j = 0; j < 4; j++) {
            float2 p0 = unpack_bf16(a0[j]), p1 = unpack_bf16(a1[j]);
            acc[j*2]   += w0 * p0.x + w1 * p1.x;
            acc[j*2+1] += w0 * p0.y + w1 * p1.y;
        }
        den += w0 + w1;
    }
    if (k < deg) {
        int s = g_csr[beg + k];
        float w = __expf(lrelu(g_as2[s] + adn));
        uint4 u = *(const uint4*)&g_z2b[(size_t)s * 32 + l8 * 4];
        const uint32_t uu[4] = {u.x, u.y, u.z, u.w};
#pragma unroll
        for (int j = 0; j < 4; j++) {
            float2 p = unpack_bf16(uu[j]);
            acc[j*2] += w * p.x; acc[j*2+1] += w * p.y;
        }
        den += w;
    }
#pragma unroll
    for (int j = 0; j < 8; j++) {
        acc[j] += __shfl_xor_sync(0xffffffff, acc[j], 8);
        acc[j] += __shfl_xor_sync(0xffffffff, acc[j], 16);
    }
    den += __shfl_xor_sync(0xffffffff, den, 8);
    den += __shfl_xor_sync(0xffffffff, den, 16);

    float pd = 0.f;
    const float* wp = Wr + l8 * 8;
#pragma unroll
    for (int j = 0; j < 8; j++) pd += acc[j] * wp[j];
    pd += __shfl_xor_sync(0xffffffff, pd, 1);
    pd += __shfl_xor_sync(0xffffffff, pd, 2);
    pd += __shfl_xor_sync(0xffffffff, pd, 4);
    if (lane == 0) bp[wid] = pd / (den + 1e-16f);
    __syncthreads();
    if (threadIdx.x == 0) {
        float s = 0.f;
#pragma unroll
        for (int j = 0; j < 8; j++) s += bp[j];
        atomicAdd(&g_out_acc, s);
        __threadfence();
        unsigned old = atomicAdd(&g_done, 1u);
        if (old == gridDim.x - 1) {
            float total = atomicExch(&g_out_acc, 0.f);
            float bwr = 0.f;
            for (int i = 0; i < 64; i++) bwr += b2[i] * Wr[i];
            out[0] = total * (1.0f / (float)N) + bwr + br[0];
            g_done = 0;
        }
    }
}

// ---------------------------------------------------------------------------
// Launch
// ---------------------------------------------------------------------------
extern "C" void kernel_launch(void* const* d_in, const int* in_sizes, int n_in,
                              void* d_out, int out_size) {
    const float* x      = (const float*)d_in[0];
    const void*  ei     = d_in[1];
    const float* W_rel  = (const float*)d_in[2];
    const float* b_rel  = (const float*)d_in[3];
    const float* W_root = (const float*)d_in[4];
    const float* W1     = (const float*)d_in[5];
    const float* a1s    = (const float*)d_in[6];
    const float* a1d    = (const float*)d_in[7];
    const float* b1     = (const float*)d_in[8];
    const float* W2     = (const float*)d_in[9];
    const float* a2s    = (const float*)d_in[10];
    const float* a2d    = (const float*)d_in[11];
    const float* b2     = (const float*)d_in[12];
    const float* Wr     = (const float*)d_in[13];
    const float* br     = (const float*)d_in[14];
    float* out          = (float*)d_out;

    float *p_nbr, *p_h, *p_h2;
    void *p_z1b, *p_z2b;
    cudaGetSymbolAddress((void**)&p_nbr, g_nbr);
    cudaGetSymbolAddress((void**)&p_h,   g_h);
    cudaGetSymbolAddress(&p_z1b, g_z1b);
    cudaGetSymbolAddress((void**)&p_h2,  g_h2);
    cudaGetSymbolAddress(&p_z2b, g_z2b);

    init_kernel<<<256, 256>>>((const int*)ei, x);

    hist_kernel<<<(E + 255) / 256, 256>>>(ei);
    scan_kernel<<<1, 1024>>>();
    fill_kernel<<<(E / 2 + 255) / 256, 256>>>();

    gather_nbr_kernel<<<(N * 32 + 255) / 256, 256>>>();
    {
        dim3 g((N + 127) / 128, 1);
        bf16_linear<128, 0><<<g, 256>>>(p_nbr, W_rel, 128, x, W_root, 128,
                                        b_rel, p_h, nullptr, nullptr, N, 128, 1);
    }
    {
        dim3 g((N + 127) / 128, 1);
        bf16_linear<64, 1><<<g, 256>>>(p_h, W1, 128, nullptr, nullptr, 0,
                                       nullptr, p_z1b, a1s, a1d, N, 64, 0);
    }
    gat1_fused<<<(N * 32 + 255) / 256, 256>>>(b1);

    {
        dim3 g((N + 127) / 128, 1);
        bf16_linear<64, 2><<<g, 256>>>(p_h2, W2, 64, nullptr, nullptr, 0,
                                       nullptr, p_z2b, a2s, a2d, N, 64, 0);
    }
    gat2_fused<<<N * 32 / 256, 256>>>(Wr, br, b2, out);
}